// round 14
// baseline (speedup 1.0000x reference)
#include <cuda_runtime.h>
#include <cstdint>

#define NB 32
#define H1 224
#define P1 (H1*H1)      // 50176
#define H2 112
#define P2 (H2*H2)      // 12544
#define H3 56
#define P3 (H3*H3)      // 3136

// padded layouts (pads never written -> stay zero)
#define BXS 232        // binx col stride, left pad 4
#define BXR 226
#define H1S 232        // h1 col stride, left pad 4 (16B-aligned uint4 stores)
#define H1R 225
#define H2S 116        // h2: pad 1
#define H2R 113

#define MAJ(a,b,c) (((a)&(b)) | ((a)&(c)) | ((b)&(c)))

// ---------------- scratch ----------------
__device__ uint32_t            g_binx[NB*BXR*BXS];
__device__ uint32_t            g_h1[NB*H1R*H1S];
__device__ unsigned long long  g_h2[NB*H2R*H2S];
__device__ int                 g_cnt[NB*128];
__device__ int                 g_done[NB];
__device__ uint32_t            g_w1[32];
__device__ uint32_t            g_w2[64*9];
__device__ unsigned long long  g_w3[128*9];
__device__ int g_S1[9*32];
__device__ int g_S2[4*64];
__device__ int g_S3[4*128];
__device__ int g_F3[128];
__device__ uint32_t g_Finit1, g_Finit2lo, g_Finit2hi;

// -------- integer threshold for sign(BN(a)), exact fp32 semantics, bisection --
__device__ __forceinline__ int f_ge0(float inv, float c0, int a)
{
    float f = __fadd_rn(__fmul_rn((float)a, inv), c0);
    return f >= 0.f;
}

__device__ __forceinline__ void calc_thresh(float g, float bb, float m, float v,
                                            int K, int* T, int* F)
{
    float inv = __fdiv_rn(g, sqrtf(__fadd_rn(v, 1e-5f)));
    float c0  = __fsub_rn(bb, __fmul_rn(m, inv));
    if (inv > 0.f) {
        int lo = -K, hi = K + 1;
        while (lo < hi) {
            int mid = lo + ((hi - lo) >> 1);
            if (f_ge0(inv, c0, mid)) hi = mid; else lo = mid + 1;
        }
        *T = lo; *F = 0;
    } else if (inv < 0.f) {
        int lo = -K - 1, hi = K;
        while (lo < hi) {
            int mid = lo + ((hi - lo + 1) >> 1);
            if (f_ge0(inv, c0, mid)) lo = mid; else hi = mid - 1;
        }
        *T = lo + 1; *F = 1;
    } else {
        if (c0 < 0.f) { *T =  K + 1;  *F = 0; }
        else          { *T = -(K+1);  *F = 0; }
    }
}

// ------- fused: binx (blocks 0..1567) + parallel precompute (blocks 1568..1573)
__global__ __launch_bounds__(256) void binx_precompute_kernel(
    const float* __restrict__ x,
    const float* w1, const float* w2, const float* w3,
    const float* g1, const float* b1, const float* m1, const float* v1,
    const float* g2, const float* b2, const float* m2, const float* v2,
    const float* g3, const float* b3, const float* m3, const float* v3)
{
    int t = threadIdx.x;
    int blk = blockIdx.x;

    if (blk < 1568) {
        int i = blk * 256 + t;                 // NB*P1/4 = 401408 exact
        int b = i / 12544, rem = i % 12544;
        int oh = rem / 56, ow0 = (rem % 56) * 4;

        const float4* xb = reinterpret_cast<const float4*>(x);
        int base = (b * 3 * P1) >> 2;
        int pidx = (oh * H1 + ow0) >> 2;
        float4 v0 = xb[base + pidx];
        float4 v1 = xb[base + (P1 >> 2) + pidx];
        float4 v2 = xb[base + (P1 >> 1) + pidx];

        uint4 o;
        o.x = (v0.x < 0.f ? 1u:0u) | (v1.x < 0.f ? 2u:0u) | (v2.x < 0.f ? 4u:0u);
        o.y = (v0.y < 0.f ? 1u:0u) | (v1.y < 0.f ? 2u:0u) | (v2.y < 0.f ? 4u:0u);
        o.z = (v0.z < 0.f ? 1u:0u) | (v1.z < 0.f ? 2u:0u) | (v2.z < 0.f ? 4u:0u);
        o.w = (v0.w < 0.f ? 1u:0u) | (v1.w < 0.f ? 2u:0u) | (v2.w < 0.f ? 4u:0u);

        *reinterpret_cast<uint4*>(&g_binx[b*(BXR*BXS) + (oh+1)*BXS + ow0 + 4]) = o;
        return;
    }

    if (blk == 1568) {
        __shared__ int sF1[32];
        if (t < 32) {
            uint32_t bits = 0;
            for (int ic = 0; ic < 3; ic++)
                for (int kh = 0; kh < 3; kh++)
                    for (int kw = 0; kw < 3; kw++)
                        if (w1[((t*3 + ic)*3 + kh)*3 + kw] < 0.f)
                            bits |= 1u << ((kh*3 + kw)*3 + ic);
            g_w1[t] = bits;
            int T, F; calc_thresh(g1[t], b1[t], m1[t], v1[t], 27, &T, &F);
            sF1[t] = F;
            for (int bt = 0; bt < 9; bt++) {
                int vt = bt / 3, hz = bt % 3;
                int inv = 0;
                if (vt == 1) inv |= (1|2|4);
                if (vt == 2) inv |= (64|128|256);
                if (hz == 1) inv |= (1|8|64);
                if (hz == 2) inv |= (4|32|256);
                int nv = 27 - 3*__popc(inv);
                int corr = 0;
                for (int tap = 0; tap < 9; tap++)
                    if ((inv >> tap) & 1) corr += __popc((bits >> (tap*3)) & 7u);
                g_S1[bt*32 + t] = ((nv - T) >> 1) + corr + 1;
            }
        }
        __syncthreads();
        if (t == 0) {
            uint32_t f = 0;
            for (int oc = 0; oc < 32; oc++) f |= ((uint32_t)sF1[oc]) << oc;
            g_Finit1 = f;
        }
        for (int j = t; j < NB*128; j += 256) g_cnt[j] = 0;
        if (t < NB) g_done[t] = 0;
        return;
    }

    if (blk == 1569) {
        __shared__ int sF2[64];
        for (int p = t; p < 576; p += 256) {
            int oc = p / 9, tap = p % 9;
            int kh = tap / 3, kw = tap % 3;
            uint32_t bits = 0;
            #pragma unroll 8
            for (int ic = 0; ic < 32; ic++)
                if (w2[((oc*32 + ic)*3 + kh)*3 + kw] < 0.f) bits |= 1u << ic;
            g_w2[p] = bits;
        }
        __syncthreads();
        if (t < 64) {
            uint32_t wt[9];
            #pragma unroll
            for (int tap = 0; tap < 9; tap++) wt[tap] = g_w2[t*9 + tap];
            int T, F; calc_thresh(g2[t], b2[t], m2[t], v2[t], 288, &T, &F);
            sF2[t] = F;
            for (int bt = 0; bt < 4; bt++) {
                int inv = 0;
                if (bt & 1) inv |= (1|2|4);
                if (bt & 2) inv |= (1|8|64);
                int nv = 32 * (9 - __popc(inv));
                int corr = 0;
                for (int tap = 0; tap < 9; tap++)
                    if ((inv >> tap) & 1) corr += __popc(wt[tap]);
                g_S2[bt*64 + t] = ((nv - T) >> 1) + corr + 1;
            }
        }
        __syncthreads();
        if (t == 0) {
            uint32_t lo = 0, hi = 0;
            for (int oc = 0; oc < 32; oc++) lo |= ((uint32_t)sF2[oc]) << oc;
            for (int oc = 0; oc < 32; oc++) hi |= ((uint32_t)sF2[oc+32]) << oc;
            g_Finit2lo = lo; g_Finit2hi = hi;
        }
        return;
    }

    {
        int q = blk - 1570;                   // 0..3
        for (int pp = t; pp < 288; pp += 256) {
            int p = q*288 + pp;
            int oc = p / 9, tap = p % 9;
            int kh = tap / 3, kw = tap % 3;
            unsigned long long bits = 0;
            #pragma unroll 8
            for (int ic = 0; ic < 64; ic++)
                if (w3[((oc*64 + ic)*3 + kh)*3 + kw] < 0.f) bits |= 1ull << ic;
            g_w3[p] = bits;
        }
        __syncthreads();
        if (t < 32) {
            int oc = q*32 + t;
            unsigned long long wt[9];
            #pragma unroll
            for (int tap = 0; tap < 9; tap++) wt[tap] = g_w3[oc*9 + tap];
            int T, F; calc_thresh(g3[oc], b3[oc], m3[oc], v3[oc], 576, &T, &F);
            g_F3[oc] = F;
            for (int bt = 0; bt < 4; bt++) {
                int inv = 0;
                if (bt & 1) inv |= (1|2|4);
                if (bt & 2) inv |= (1|8|64);
                int nv = 64 * (9 - __popc(inv));
                int corr = 0;
                for (int tap = 0; tap < 9; tap++)
                    if ((inv >> tap) & 1) corr += __popcll(wt[tap]);
                g_S3[bt*128 + oc] = ((nv - T) >> 1) + corr + 1;
            }
        }
        return;
    }
}

// --------- layer 1: 3ch -> 32ch, stride 1, 4 px/thread, incremental window ---
#define L1CM 0x070381C0u

__global__ __launch_bounds__(256) void layer1_kernel()
{
    __shared__ uint32_t sw[32];
    __shared__ int sS[9*32];
    if (threadIdx.x < 32) sw[threadIdx.x] = g_w1[threadIdx.x];
    for (int j = threadIdx.x; j < 9*32; j += blockDim.x) sS[j] = g_S1[j];
    __syncthreads();

    int i = blockIdx.x * blockDim.x + threadIdx.x;   // NB*224*56 = 401408 exact
    int b = i / 12544, rem = i % 12544;
    int oh = rem / 56, g = rem % 56;
    int ow0 = g * 4;

    const uint32_t* bx = g_binx + b*(BXR*BXS) + oh*BXS + ow0 + 3;
    uint32_t c[3][6];
    #pragma unroll
    for (int kh = 0; kh < 3; kh++)
        #pragma unroll
        for (int m = 0; m < 6; m++) c[kh][m] = bx[kh*BXS + m];

    uint32_t xv0 = 0;
    #pragma unroll
    for (int kh = 0; kh < 3; kh++)
        #pragma unroll
        for (int kw = 0; kw < 3; kw++)
            xv0 |= c[kh][kw] << ((kh*3 + kw)*3);

    uint32_t xv1 = ((xv0 >> 3) & ~L1CM) | (c[0][3]<<6) | (c[1][3]<<15) | (c[2][3]<<24);
    uint32_t xv2 = ((xv1 >> 3) & ~L1CM) | (c[0][4]<<6) | (c[1][4]<<15) | (c[2][4]<<24);
    uint32_t xv3 = ((xv2 >> 3) & ~L1CM) | (c[0][5]<<6) | (c[1][5]<<15) | (c[2][5]<<24);

    int vt = (oh == 0) ? 1 : ((oh == 223) ? 2 : 0);
    const int* Sm = &sS[(vt*3) * 32];
    const int* Sa = &sS[(vt*3 + ((g == 0)  ? 1 : 0)) * 32];
    const int* Sb = &sS[(vt*3 + ((g == 55) ? 2 : 0)) * 32];

    uint32_t fi = g_Finit1;
    uint32_t o0 = fi, o1 = fi, o2 = fi, o3 = fi;
    #pragma unroll 8
    for (int oc = 0; oc < 32; oc++) {
        uint32_t w = sw[oc];
        uint32_t mb = 1u << oc;
        int sm = Sm[oc];
        if (__popc(xv0 ^ w) >= Sa[oc]) o0 ^= mb;
        if (__popc(xv1 ^ w) >= sm)     o1 ^= mb;
        if (__popc(xv2 ^ w) >= sm)     o2 ^= mb;
        if (__popc(xv3 ^ w) >= Sb[oc]) o3 ^= mb;
    }
    uint4 ov = make_uint4(o0, o1, o2, o3);
    *reinterpret_cast<uint4*>(
        &g_h1[b*(H1R*H1S) + (oh+1)*H1S + (ow0+4)]) = ov;
}

// ------ layer 2: 32ch -> 64ch, stride 2, 1 px/thread, 32 oc per block-group --
__global__ __launch_bounds__(256) void layer2_kernel()
{
    __shared__ uint4 sw4[32*3];
    __shared__ int sS[4*32];
    int grp = blockIdx.y;

    for (int j = threadIdx.x; j < 32*3; j += blockDim.x) {
        int oc = j / 3, k = j % 3, base = (grp*32 + oc)*9 + k*4;
        uint4 v;
        v.x = g_w2[base];
        v.y = (k*4 + 1 < 9) ? g_w2[base+1] : 0u;
        v.z = (k*4 + 2 < 9) ? g_w2[base+2] : 0u;
        v.w = (k*4 + 3 < 9) ? g_w2[base+3] : 0u;
        sw4[j] = v;
    }
    for (int j = threadIdx.x; j < 4*32; j += blockDim.x) {
        int bt = j >> 5, oc = j & 31;
        sS[j] = g_S2[bt*64 + grp*32 + oc];
    }
    __syncthreads();

    int i = blockIdx.x * blockDim.x + threadIdx.x;   // NB*P2 = 401408 exact
    int b = i / 12544, rem = i % 12544;
    int oh = rem / 112, ow = rem % 112;

    const uint32_t* h1 = g_h1 + b*(H1R*H1S) + (2*oh)*H1S + 2*ow + 3;
    uint32_t x00 = h1[0],      x01 = h1[1],       x02 = h1[2];
    uint32_t x10 = h1[H1S],    x11 = h1[H1S+1],   x12 = h1[H1S+2];
    uint32_t x20 = h1[2*H1S],  x21 = h1[2*H1S+1], x22 = h1[2*H1S+2];

    int bt = ((oh == 0) ? 1 : 0) + ((ow == 0) ? 2 : 0);
    const int* Sp = &sS[bt * 32];

    uint32_t acc = grp ? g_Finit2hi : g_Finit2lo;

    #pragma unroll 8
    for (int oc = 0; oc < 32; oc++) {
        uint4 a = sw4[oc*3], bq = sw4[oc*3+1], cq = sw4[oc*3+2];
        uint32_t t0 = x00^a.x,  t1 = x01^a.y,  t2 = x02^a.z;
        uint32_t t3 = x10^a.w,  t4 = x11^bq.x, t5 = x12^bq.y;
        uint32_t t6 = x20^bq.z, t7 = x21^bq.w, t8 = x22^cq.x;
        uint32_t s0 = t0^t1^t2, k0 = MAJ(t0,t1,t2);
        uint32_t s1 = t3^t4^t5, k1 = MAJ(t3,t4,t5);
        uint32_t s2 = t6^t7^t8, k2 = MAJ(t6,t7,t8);
        uint32_t s3 = s0^s1^s2, k3 = MAJ(s0,s1,s2);
        uint32_t s4 = k0^k1^k2, k4 = MAJ(k0,k1,k2);
        int tot = __popc(s3) + ((__popc(k3) + __popc(s4)) << 1)
                + (__popc(k4) << 2);
        if (tot >= Sp[oc]) acc ^= 1u << oc;
    }
    uint32_t* dst = reinterpret_cast<uint32_t*>(
        &g_h2[b*(H2R*H2S) + (oh+1)*H2S + (ow+1)]);
    dst[grp] = acc;
}

// ---- layer 3: 64ch -> 128ch; warp = 32 px, 32 oc (quarter); CSA popcount ----
// Dual-oc interleaved inner loop (k and k+16) for explicit ILP.
// 49 blocks per image; last completing block computes fc for that image.
#define L3CHAIN(WP, TOT) { \
    ulonglong2 q0 = (WP)[0], q1 = (WP)[1], q2 = (WP)[2], q3 = (WP)[3], q4 = (WP)[4]; \
    unsigned long long t0 = c00^q0.x, t1 = c01^q0.y, t2 = c02^q1.x; \
    unsigned long long t3 = c10^q1.y, t4 = c11^q2.x, t5 = c12^q2.y; \
    unsigned long long t6 = c20^q3.x, t7 = c21^q3.y, t8 = c22^q4.x; \
    unsigned long long s0w = t0^t1^t2, k0w = MAJ(t0,t1,t2); \
    unsigned long long s1w = t3^t4^t5, k1w = MAJ(t3,t4,t5); \
    unsigned long long s2w = t6^t7^t8, k2w = MAJ(t6,t7,t8); \
    unsigned long long s3w = s0w^s1w^s2w, k3w = MAJ(s0w,s1w,s2w); \
    unsigned long long s4w = k0w^k1w^k2w, k4w = MAJ(k0w,k1w,k2w); \
    (TOT) = __popcll(s3w) + ((__popcll(k3w) + __popcll(s4w)) << 1) \
          + (__popcll(k4w) << 2); }

__global__ __launch_bounds__(256) void layer3_kernel(
    const float* __restrict__ fcw,
    const float* __restrict__ fcb,
    float* __restrict__ out)
{
    __shared__ ulonglong2 sw2[128*5];
    __shared__ int sS[4*128];
    __shared__ int slast;
    for (int j = threadIdx.x; j < 128*5; j += blockDim.x) {
        int oc = j / 5, s2 = j % 5, base = oc*9 + s2*2;
        ulonglong2 v;
        v.x = g_w3[base];
        v.y = (s2*2 + 1 < 9) ? g_w3[base+1] : 0ull;
        sw2[j] = v;
    }
    for (int j = threadIdx.x; j < 4*128; j += blockDim.x) sS[j] = g_S3[j];
    __syncthreads();

    int i = blockIdx.x * blockDim.x + threadIdx.x;   // 1568 blocks x 256
    int wid = i >> 5, lane = i & 31;
    int quarter = wid & 3;
    int pw = wid >> 2;              // 0..3135 pixel-warps (98 per image)
    int b = pw / 98;                // uniform per block (49 blocks/image)
    int q = (pw % 98) * 32 + lane;
    int oh = q / H3, ow = q % H3;

    const unsigned long long* h2 = g_h2 + b*(H2R*H2S) + (2*oh)*H2S + 2*ow;
    unsigned long long c00 = h2[0],       c01 = h2[1],       c02 = h2[2];
    unsigned long long c10 = h2[H2S],     c11 = h2[H2S+1],   c12 = h2[H2S+2];
    unsigned long long c20 = h2[2*H2S],   c21 = h2[2*H2S+1], c22 = h2[2*H2S+2];

    int bt = ((oh == 0) ? 1 : 0) + ((ow == 0) ? 2 : 0);
    const int* Sp = &sS[bt*128 + quarter*32];
    const ulonglong2* wbase = &sw2[quarter*32*5];

    int r = 0;
    #pragma unroll 2
    for (int k = 0; k < 16; k++) {
        int totA, totB;
        L3CHAIN(wbase + k*5,        totA)
        L3CHAIN(wbase + (k+16)*5,   totB)
        unsigned balA = __ballot_sync(0xFFFFFFFFu, totA >= Sp[k]);
        unsigned balB = __ballot_sync(0xFFFFFFFFu, totB >= Sp[k+16]);
        if (k == lane)      r = __popc(balA);
        if (k + 16 == lane) r = __popc(balB);
    }

    int oc = quarter*32 + lane;
    if (g_F3[oc]) r = 32 - r;
    atomicAdd(&g_cnt[b*128 + oc], r);

    // ---- fused fc: last completing block of this image reduces g_cnt ----
    __syncthreads();
    if (threadIdx.x == 0) {
        __threadfence();
        int old = atomicAdd(&g_done[b], 1);
        slast = (old == 48);
    }
    __syncthreads();
    if (slast && threadIdx.x < 32) {
        float u0 = 0.f, u1 = 0.f;
        #pragma unroll
        for (int j = 0; j < 4; j++) {
            int c = lane * 4 + j;
            float mean = (float)(P3 - 2*g_cnt[b*128 + c]) / (float)P3;
            u0 += mean * fcw[c];
            u1 += mean * fcw[128 + c];
        }
        #pragma unroll
        for (int off = 16; off > 0; off >>= 1) {
            u0 += __shfl_down_sync(0xFFFFFFFFu, u0, off);
            u1 += __shfl_down_sync(0xFFFFFFFFu, u1, off);
        }
        if (lane == 0) {
            out[b*2]     = fcb[0] + u0;
            out[b*2 + 1] = fcb[1] + u1;
        }
    }
}

// ---------------- launch ----------------
extern "C" void kernel_launch(void* const* d_in, const int* in_sizes, int n_in,
                              void* d_out, int out_size)
{
    const float* x   = (const float*)d_in[0];
    const float* w1  = (const float*)d_in[1];
    const float* w2  = (const float*)d_in[2];
    const float* w3  = (const float*)d_in[3];
    const float* g1  = (const float*)d_in[4];
    const float* b1  = (const float*)d_in[5];
    const float* m1  = (const float*)d_in[6];
    const float* v1  = (const float*)d_in[7];
    const float* g2  = (const float*)d_in[8];
    const float* b2  = (const float*)d_in[9];
    const float* m2  = (const float*)d_in[10];
    const float* v2  = (const float*)d_in[11];
    const float* g3  = (const float*)d_in[12];
    const float* b3  = (const float*)d_in[13];
    const float* m3  = (const float*)d_in[14];
    const float* v3  = (const float*)d_in[15];
    const float* fcw = (const float*)d_in[16];
    const float* fcb = (const float*)d_in[17];
    float* out = (float*)d_out;

    binx_precompute_kernel<<<1574, 256>>>(x, w1, w2, w3,
                                          g1, b1, m1, v1,
                                          g2, b2, m2, v2,
                                          g3, b3, m3, v3);

    layer1_kernel<<<1568, 256>>>();               // 4 px/thread
    layer2_kernel<<<dim3(1568, 2), 256>>>();      // 1 px/thread, 32 oc groups
    layer3_kernel<<<1568, 256>>>(fcw, fcb, out);  // dual-oc ILP, fc fused
}

// round 15
// speedup vs baseline: 1.0725x; 1.0725x over previous
#include <cuda_runtime.h>
#include <cstdint>

#define NB 32
#define H1 224
#define P1 (H1*H1)      // 50176
#define H2 112
#define P2 (H2*H2)      // 12544
#define H3 56
#define P3 (H3*H3)      // 3136

// padded layouts (pads never written -> stay zero)
#define BXS 232
#define BXR 226
#define H1S 232
#define H1R 225
#define H2S 116
#define H2R 113

#define MAJ(a,b,c) (((a)&(b)) | ((a)&(c)) | ((b)&(c)))

// ---------------- scratch ----------------
__device__ uint32_t            g_binx[NB*BXR*BXS];
__device__ uint32_t            g_h1[NB*H1R*H1S];
__device__ unsigned long long  g_h2[NB*H2R*H2S];
__device__ int                 g_cnt[NB*128];
__device__ int                 g_done[NB];
__device__ int                 d_l1[NB];
__device__ int                 d_l2[NB];
__device__ uint32_t            g_w1[32];
__device__ uint32_t            g_w2[64*9];
__device__ unsigned long long  g_w3[128*9];
__device__ int g_S1[9*32];
__device__ int g_S2[4*64];
__device__ int g_S3[4*128];
__device__ int g_F3[128];
__device__ uint32_t g_Finit1, g_Finit2lo, g_Finit2hi;

// -------- integer threshold for sign(BN(a)), exact fp32 semantics, bisection --
__device__ __forceinline__ int f_ge0(float inv, float c0, int a)
{
    float f = __fadd_rn(__fmul_rn((float)a, inv), c0);
    return f >= 0.f;
}

__device__ __forceinline__ void calc_thresh(float g, float bb, float m, float v,
                                            int K, int* T, int* F)
{
    float inv = __fdiv_rn(g, sqrtf(__fadd_rn(v, 1e-5f)));
    float c0  = __fsub_rn(bb, __fmul_rn(m, inv));
    if (inv > 0.f) {
        int lo = -K, hi = K + 1;
        while (lo < hi) {
            int mid = lo + ((hi - lo) >> 1);
            if (f_ge0(inv, c0, mid)) hi = mid; else lo = mid + 1;
        }
        *T = lo; *F = 0;
    } else if (inv < 0.f) {
        int lo = -K - 1, hi = K;
        while (lo < hi) {
            int mid = lo + ((hi - lo + 1) >> 1);
            if (f_ge0(inv, c0, mid)) lo = mid; else hi = mid - 1;
        }
        *T = lo + 1; *F = 1;
    } else {
        if (c0 < 0.f) { *T =  K + 1;  *F = 0; }
        else          { *T = -(K+1);  *F = 0; }
    }
}

// ---- pipeline sync helpers ----
__device__ __forceinline__ void block_wait(int* flag, int target)
{
    if (threadIdx.x == 0) {
        while (true) {
            int v;
            asm volatile("ld.acquire.gpu.b32 %0, [%1];" : "=r"(v) : "l"(flag));
            if (v >= target) break;
            __nanosleep(128);
        }
    }
    __syncthreads();
}

__device__ __forceinline__ void block_signal(int* flag)
{
    __syncthreads();
    if (threadIdx.x == 0) {
        __threadfence();
        atomicAdd(flag, 1);
    }
}

// ------- K1: binx (blocks 0..1567) + parallel precompute (blocks 1568..1573)
__global__ __launch_bounds__(256) void binx_precompute_kernel(
    const float* __restrict__ x,
    const float* w1, const float* w2, const float* w3,
    const float* g1, const float* b1, const float* m1, const float* v1,
    const float* g2, const float* b2, const float* m2, const float* v2,
    const float* g3, const float* b3, const float* m3, const float* v3)
{
    int t = threadIdx.x;
    int blk = blockIdx.x;

    if (blk < 1568) {
        int i = blk * 256 + t;                 // NB*P1/4 = 401408 exact
        int b = i / 12544, rem = i % 12544;
        int oh = rem / 56, ow0 = (rem % 56) * 4;

        const float4* xb = reinterpret_cast<const float4*>(x);
        int base = (b * 3 * P1) >> 2;
        int pidx = (oh * H1 + ow0) >> 2;
        float4 v0 = xb[base + pidx];
        float4 v1 = xb[base + (P1 >> 2) + pidx];
        float4 v2 = xb[base + (P1 >> 1) + pidx];

        uint4 o;
        o.x = (v0.x < 0.f ? 1u:0u) | (v1.x < 0.f ? 2u:0u) | (v2.x < 0.f ? 4u:0u);
        o.y = (v0.y < 0.f ? 1u:0u) | (v1.y < 0.f ? 2u:0u) | (v2.y < 0.f ? 4u:0u);
        o.z = (v0.z < 0.f ? 1u:0u) | (v1.z < 0.f ? 2u:0u) | (v2.z < 0.f ? 4u:0u);
        o.w = (v0.w < 0.f ? 1u:0u) | (v1.w < 0.f ? 2u:0u) | (v2.w < 0.f ? 4u:0u);

        *reinterpret_cast<uint4*>(&g_binx[b*(BXR*BXS) + (oh+1)*BXS + ow0 + 4]) = o;
        return;
    }

    if (blk == 1568) {
        __shared__ int sF1[32];
        if (t < 32) {
            uint32_t bits = 0;
            for (int ic = 0; ic < 3; ic++)
                for (int kh = 0; kh < 3; kh++)
                    for (int kw = 0; kw < 3; kw++)
                        if (w1[((t*3 + ic)*3 + kh)*3 + kw] < 0.f)
                            bits |= 1u << ((kh*3 + kw)*3 + ic);
            g_w1[t] = bits;
            int T, F; calc_thresh(g1[t], b1[t], m1[t], v1[t], 27, &T, &F);
            sF1[t] = F;
            for (int bt = 0; bt < 9; bt++) {
                int vt = bt / 3, hz = bt % 3;
                int inv = 0;
                if (vt == 1) inv |= (1|2|4);
                if (vt == 2) inv |= (64|128|256);
                if (hz == 1) inv |= (1|8|64);
                if (hz == 2) inv |= (4|32|256);
                int nv = 27 - 3*__popc(inv);
                int corr = 0;
                for (int tap = 0; tap < 9; tap++)
                    if ((inv >> tap) & 1) corr += __popc((bits >> (tap*3)) & 7u);
                g_S1[bt*32 + t] = ((nv - T) >> 1) + corr + 1;
            }
        }
        __syncthreads();
        if (t == 0) {
            uint32_t f = 0;
            for (int oc = 0; oc < 32; oc++) f |= ((uint32_t)sF1[oc]) << oc;
            g_Finit1 = f;
        }
        // safety re-zero (self-cleaned by pipeline, but idempotent)
        for (int j = t; j < NB*128; j += 256) g_cnt[j] = 0;
        if (t < NB) { g_done[t] = 0; d_l1[t] = 0; d_l2[t] = 0; }
        return;
    }

    if (blk == 1569) {
        __shared__ int sF2[64];
        for (int p = t; p < 576; p += 256) {
            int oc = p / 9, tap = p % 9;
            int kh = tap / 3, kw = tap % 3;
            uint32_t bits = 0;
            #pragma unroll 8
            for (int ic = 0; ic < 32; ic++)
                if (w2[((oc*32 + ic)*3 + kh)*3 + kw] < 0.f) bits |= 1u << ic;
            g_w2[p] = bits;
        }
        __syncthreads();
        if (t < 64) {
            uint32_t wt[9];
            #pragma unroll
            for (int tap = 0; tap < 9; tap++) wt[tap] = g_w2[t*9 + tap];
            int T, F; calc_thresh(g2[t], b2[t], m2[t], v2[t], 288, &T, &F);
            sF2[t] = F;
            for (int bt = 0; bt < 4; bt++) {
                int inv = 0;
                if (bt & 1) inv |= (1|2|4);
                if (bt & 2) inv |= (1|8|64);
                int nv = 32 * (9 - __popc(inv));
                int corr = 0;
                for (int tap = 0; tap < 9; tap++)
                    if ((inv >> tap) & 1) corr += __popc(wt[tap]);
                g_S2[bt*64 + t] = ((nv - T) >> 1) + corr + 1;
            }
        }
        __syncthreads();
        if (t == 0) {
            uint32_t lo = 0, hi = 0;
            for (int oc = 0; oc < 32; oc++) lo |= ((uint32_t)sF2[oc]) << oc;
            for (int oc = 0; oc < 32; oc++) hi |= ((uint32_t)sF2[oc+32]) << oc;
            g_Finit2lo = lo; g_Finit2hi = hi;
        }
        return;
    }

    {
        int q = blk - 1570;                   // 0..3
        for (int pp = t; pp < 288; pp += 256) {
            int p = q*288 + pp;
            int oc = p / 9, tap = p % 9;
            int kh = tap / 3, kw = tap % 3;
            unsigned long long bits = 0;
            #pragma unroll 8
            for (int ic = 0; ic < 64; ic++)
                if (w3[((oc*64 + ic)*3 + kh)*3 + kw] < 0.f) bits |= 1ull << ic;
            g_w3[p] = bits;
        }
        __syncthreads();
        if (t < 32) {
            int oc = q*32 + t;
            unsigned long long wt[9];
            #pragma unroll
            for (int tap = 0; tap < 9; tap++) wt[tap] = g_w3[oc*9 + tap];
            int T, F; calc_thresh(g3[oc], b3[oc], m3[oc], v3[oc], 576, &T, &F);
            g_F3[oc] = F;
            for (int bt = 0; bt < 4; bt++) {
                int inv = 0;
                if (bt & 1) inv |= (1|2|4);
                if (bt & 2) inv |= (1|8|64);
                int nv = 64 * (9 - __popc(inv));
                int corr = 0;
                for (int tap = 0; tap < 9; tap++)
                    if ((inv >> tap) & 1) corr += __popcll(wt[tap]);
                g_S3[bt*128 + oc] = ((nv - T) >> 1) + corr + 1;
            }
        }
        return;
    }
}

// ---- K2: fused pipeline. blocks [0,1568) = L1, [1568,4704) = L2,
//      [4704,6272) = L3 (+fc). Per-image flags order the layers; all
//      dependencies point >=1519 blocks backwards, so in-order CTA issue
//      guarantees progress.
#define L1CM 0x070381C0u

__global__ __launch_bounds__(256) void pipeline_kernel(
    const float* __restrict__ fcw,
    const float* __restrict__ fcb,
    float* __restrict__ out)
{
    __shared__ __align__(16) char smemraw[12544];
    int t = threadIdx.x;
    int blk = blockIdx.x;

    if (blk < 1568) {
        // ---------------- L1 role: 4 px/thread ----------------
        uint32_t* sw = reinterpret_cast<uint32_t*>(smemraw);
        int* sS = reinterpret_cast<int*>(smemraw + 128);
        if (t < 32) sw[t] = g_w1[t];
        for (int j = t; j < 9*32; j += 256) sS[j] = g_S1[j];
        __syncthreads();

        int i = blk * 256 + t;                 // NB*224*56 exact
        int b = i / 12544, rem = i % 12544;
        int oh = rem / 56, g = rem % 56;
        int ow0 = g * 4;

        const uint32_t* bx = g_binx + b*(BXR*BXS) + oh*BXS + ow0 + 3;
        uint32_t c[3][6];
        #pragma unroll
        for (int kh = 0; kh < 3; kh++)
            #pragma unroll
            for (int m = 0; m < 6; m++) c[kh][m] = bx[kh*BXS + m];

        uint32_t xv0 = 0;
        #pragma unroll
        for (int kh = 0; kh < 3; kh++)
            #pragma unroll
            for (int kw = 0; kw < 3; kw++)
                xv0 |= c[kh][kw] << ((kh*3 + kw)*3);

        uint32_t xv1 = ((xv0 >> 3) & ~L1CM) | (c[0][3]<<6) | (c[1][3]<<15) | (c[2][3]<<24);
        uint32_t xv2 = ((xv1 >> 3) & ~L1CM) | (c[0][4]<<6) | (c[1][4]<<15) | (c[2][4]<<24);
        uint32_t xv3 = ((xv2 >> 3) & ~L1CM) | (c[0][5]<<6) | (c[1][5]<<15) | (c[2][5]<<24);

        int vt = (oh == 0) ? 1 : ((oh == 223) ? 2 : 0);
        const int* Sm = &sS[(vt*3) * 32];
        const int* Sa = &sS[(vt*3 + ((g == 0)  ? 1 : 0)) * 32];
        const int* Sb = &sS[(vt*3 + ((g == 55) ? 2 : 0)) * 32];

        uint32_t fi = g_Finit1;
        uint32_t o0 = fi, o1 = fi, o2 = fi, o3 = fi;
        #pragma unroll 8
        for (int oc = 0; oc < 32; oc++) {
            uint32_t w = sw[oc];
            uint32_t mb = 1u << oc;
            int sm = Sm[oc];
            if (__popc(xv0 ^ w) >= Sa[oc]) o0 ^= mb;
            if (__popc(xv1 ^ w) >= sm)     o1 ^= mb;
            if (__popc(xv2 ^ w) >= sm)     o2 ^= mb;
            if (__popc(xv3 ^ w) >= Sb[oc]) o3 ^= mb;
        }
        uint4 ov = make_uint4(o0, o1, o2, o3);
        *reinterpret_cast<uint4*>(
            &g_h1[b*(H1R*H1S) + (oh+1)*H1S + (ow0+4)]) = ov;

        block_signal(&d_l1[b]);
        return;
    }

    if (blk < 4704) {
        // ---------------- L2 role: 1 px/thread, 32 oc per group ----------------
        int lblk = blk - 1568;         // 0..3135
        int b = lblk / 98;
        int sub = lblk % 98;
        int grp = sub / 49;
        int sub2 = sub % 49;

        block_wait(&d_l1[b], 49);

        uint4* sw4 = reinterpret_cast<uint4*>(smemraw);
        int* sS = reinterpret_cast<int*>(smemraw + 1536);
        for (int j = t; j < 32*3; j += 256) {
            int oc = j / 3, k = j % 3, base = (grp*32 + oc)*9 + k*4;
            uint4 v;
            v.x = g_w2[base];
            v.y = (k*4 + 1 < 9) ? g_w2[base+1] : 0u;
            v.z = (k*4 + 2 < 9) ? g_w2[base+2] : 0u;
            v.w = (k*4 + 3 < 9) ? g_w2[base+3] : 0u;
            sw4[j] = v;
        }
        for (int j = t; j < 4*32; j += 256) {
            int bt = j >> 5, oc = j & 31;
            sS[j] = g_S2[bt*64 + grp*32 + oc];
        }
        __syncthreads();

        int i = (b*49 + sub2) * 256 + t;
        int rem = i % 12544;
        int oh = rem / 112, ow = rem % 112;

        const uint32_t* h1 = g_h1 + b*(H1R*H1S) + (2*oh)*H1S + 2*ow + 3;
        uint32_t x00 = h1[0],      x01 = h1[1],       x02 = h1[2];
        uint32_t x10 = h1[H1S],    x11 = h1[H1S+1],   x12 = h1[H1S+2];
        uint32_t x20 = h1[2*H1S],  x21 = h1[2*H1S+1], x22 = h1[2*H1S+2];

        int bt = ((oh == 0) ? 1 : 0) + ((ow == 0) ? 2 : 0);
        const int* Sp = &sS[bt * 32];

        uint32_t acc = grp ? g_Finit2hi : g_Finit2lo;

        #pragma unroll 8
        for (int oc = 0; oc < 32; oc++) {
            uint4 a = sw4[oc*3], bq = sw4[oc*3+1], cq = sw4[oc*3+2];
            uint32_t t0 = x00^a.x,  t1 = x01^a.y,  t2 = x02^a.z;
            uint32_t t3 = x10^a.w,  t4 = x11^bq.x, t5 = x12^bq.y;
            uint32_t t6 = x20^bq.z, t7 = x21^bq.w, t8 = x22^cq.x;
            uint32_t s0 = t0^t1^t2, k0 = MAJ(t0,t1,t2);
            uint32_t s1 = t3^t4^t5, k1 = MAJ(t3,t4,t5);
            uint32_t s2 = t6^t7^t8, k2 = MAJ(t6,t7,t8);
            uint32_t s3 = s0^s1^s2, k3 = MAJ(s0,s1,s2);
            uint32_t s4 = k0^k1^k2, k4 = MAJ(k0,k1,k2);
            int tot = __popc(s3) + ((__popc(k3) + __popc(s4)) << 1)
                    + (__popc(k4) << 2);
            if (tot >= Sp[oc]) acc ^= 1u << oc;
        }
        uint32_t* dst = reinterpret_cast<uint32_t*>(
            &g_h2[b*(H2R*H2S) + (oh+1)*H2S + (ow+1)]);
        dst[grp] = acc;

        block_signal(&d_l2[b]);
        return;
    }

    {
        // ------- L3 role: warp = 32 px, 32 oc (quarter); CSA popcount + fc ----
        int lblk = blk - 4704;         // 0..1567
        int b = lblk / 49;

        block_wait(&d_l2[b], 98);

        ulonglong2* sw2 = reinterpret_cast<ulonglong2*>(smemraw);
        int* sS = reinterpret_cast<int*>(smemraw + 10240);
        for (int j = t; j < 128*5; j += 256) {
            int oc = j / 5, s2 = j % 5, base = oc*9 + s2*2;
            ulonglong2 v;
            v.x = g_w3[base];
            v.y = (s2*2 + 1 < 9) ? g_w3[base+1] : 0ull;
            sw2[j] = v;
        }
        for (int j = t; j < 4*128; j += 256) sS[j] = g_S3[j];
        __syncthreads();

        int i = lblk * 256 + t;
        int wid = i >> 5, lane = i & 31;
        int quarter = wid & 3;
        int pw = wid >> 2;
        int q = (pw % 98) * 32 + lane;
        int oh = q / H3, ow = q % H3;

        const unsigned long long* h2 = g_h2 + b*(H2R*H2S) + (2*oh)*H2S + 2*ow;
        unsigned long long c00 = h2[0],       c01 = h2[1],       c02 = h2[2];
        unsigned long long c10 = h2[H2S],     c11 = h2[H2S+1],   c12 = h2[H2S+2];
        unsigned long long c20 = h2[2*H2S],   c21 = h2[2*H2S+1], c22 = h2[2*H2S+2];

        int bt = ((oh == 0) ? 1 : 0) + ((ow == 0) ? 2 : 0);
        const int* Sp = &sS[bt*128 + quarter*32];
        const ulonglong2* wbase = &sw2[quarter*32*5];

        int r = 0;
        #pragma unroll 4
        for (int k = 0; k < 32; k++) {
            const ulonglong2* wp = wbase + k*5;
            ulonglong2 q0 = wp[0], q1 = wp[1], q2 = wp[2], q3 = wp[3], q4 = wp[4];
            unsigned long long t0 = c00^q0.x, t1 = c01^q0.y, t2 = c02^q1.x;
            unsigned long long t3 = c10^q1.y, t4 = c11^q2.x, t5 = c12^q2.y;
            unsigned long long t6 = c20^q3.x, t7 = c21^q3.y, t8 = c22^q4.x;
            unsigned long long s0w = t0^t1^t2, k0w = MAJ(t0,t1,t2);
            unsigned long long s1w = t3^t4^t5, k1w = MAJ(t3,t4,t5);
            unsigned long long s2w = t6^t7^t8, k2w = MAJ(t6,t7,t8);
            unsigned long long s3w = s0w^s1w^s2w, k3w = MAJ(s0w,s1w,s2w);
            unsigned long long s4w = k0w^k1w^k2w, k4w = MAJ(k0w,k1w,k2w);
            int tot = __popcll(s3w) + ((__popcll(k3w) + __popcll(s4w)) << 1)
                    + (__popcll(k4w) << 2);
            unsigned bal = __ballot_sync(0xFFFFFFFFu, tot >= Sp[k]);
            if (k == lane) r = __popc(bal);
        }

        int oc = quarter*32 + lane;
        if (g_F3[oc]) r = 32 - r;
        atomicAdd(&g_cnt[b*128 + oc], r);

        // ---- fused fc + self-clean: last completing block of this image ----
        __shared__ int slast;
        __syncthreads();
        if (t == 0) {
            __threadfence();
            int old = atomicAdd(&g_done[b], 1);
            slast = (old == 48);
        }
        __syncthreads();
        if (slast) {
            if (t < 32) {
                float u0 = 0.f, u1 = 0.f;
                #pragma unroll
                for (int j = 0; j < 4; j++) {
                    int c = lane * 4 + j;
                    float mean = (float)(P3 - 2*g_cnt[b*128 + c]) / (float)P3;
                    u0 += mean * fcw[c];
                    u1 += mean * fcw[128 + c];
                }
                #pragma unroll
                for (int off = 16; off > 0; off >>= 1) {
                    u0 += __shfl_down_sync(0xFFFFFFFFu, u0, off);
                    u1 += __shfl_down_sync(0xFFFFFFFFu, u1, off);
                }
                if (lane == 0) {
                    out[b*2]     = fcb[0] + u0;
                    out[b*2 + 1] = fcb[1] + u1;
                }
            }
            __syncthreads();
            // self-clean for deterministic graph replay
            if (t < 128) g_cnt[b*128 + t] = 0;
            if (t == 0) { g_done[b] = 0; d_l1[b] = 0; d_l2[b] = 0; }
        }
    }
}

// ---------------- launch ----------------
extern "C" void kernel_launch(void* const* d_in, const int* in_sizes, int n_in,
                              void* d_out, int out_size)
{
    const float* x   = (const float*)d_in[0];
    const float* w1  = (const float*)d_in[1];
    const float* w2  = (const float*)d_in[2];
    const float* w3  = (const float*)d_in[3];
    const float* g1  = (const float*)d_in[4];
    const float* b1  = (const float*)d_in[5];
    const float* m1  = (const float*)d_in[6];
    const float* v1  = (const float*)d_in[7];
    const float* g2  = (const float*)d_in[8];
    const float* b2  = (const float*)d_in[9];
    const float* m2  = (const float*)d_in[10];
    const float* v2  = (const float*)d_in[11];
    const float* g3  = (const float*)d_in[12];
    const float* b3  = (const float*)d_in[13];
    const float* m3  = (const float*)d_in[14];
    const float* v3  = (const float*)d_in[15];
    const float* fcw = (const float*)d_in[16];
    const float* fcb = (const float*)d_in[17];
    float* out = (float*)d_out;

    binx_precompute_kernel<<<1574, 256>>>(x, w1, w2, w3,
                                          g1, b1, m1, v1,
                                          g2, b2, m2, v2,
                                          g3, b3, m3, v3);

    pipeline_kernel<<<6272, 256>>>(fcw, fcb, out);   // L1+L2+L3+fc, block-role
}

// round 16
// speedup vs baseline: 1.0957x; 1.0216x over previous
#include <cuda_runtime.h>
#include <cstdint>

#define NB 32
#define H1 224
#define P1 (H1*H1)      // 50176
#define H2 112
#define P2 (H2*H2)      // 12544
#define H3 56
#define P3 (H3*H3)      // 3136

// padded layouts (pads never written -> stay zero)
#define BXS 232
#define BXR 226
#define H1S 232
#define H1R 225
#define H2S 116
#define H2R 113

#define MAJ(a,b,c) (((a)&(b)) | ((a)&(c)) | ((b)&(c)))

// ---------------- scratch ----------------
__device__ uint32_t            g_binx[NB*BXR*BXS];
__device__ uint32_t            g_h1[NB*H1R*H1S];
__device__ unsigned long long  g_h2[NB*H2R*H2S];
__device__ int                 g_cnt[NB*128];
__device__ int                 g_done[NB];
__device__ int                 d_bx[NB];
__device__ int                 d_l1[NB];
__device__ int                 d_l2[NB];
__device__ int                 d_pw1, d_pw2, d_pw3;
__device__ int                 g_fcdone;
__device__ uint32_t            g_w1[32];
__device__ uint32_t            g_w2[64*9];
__device__ unsigned long long  g_w3[128*9];
__device__ int g_S1[9*32];
__device__ int g_S2[4*64];
__device__ int g_S3[4*128];
__device__ int g_F3[128];
__device__ uint32_t g_Finit1, g_Finit2lo, g_Finit2hi;

// -------- integer threshold for sign(BN(a)), exact fp32 semantics, bisection --
__device__ __forceinline__ int f_ge0(float inv, float c0, int a)
{
    float f = __fadd_rn(__fmul_rn((float)a, inv), c0);
    return f >= 0.f;
}

__device__ __forceinline__ void calc_thresh(float g, float bb, float m, float v,
                                            int K, int* T, int* F)
{
    float inv = __fdiv_rn(g, sqrtf(__fadd_rn(v, 1e-5f)));
    float c0  = __fsub_rn(bb, __fmul_rn(m, inv));
    if (inv > 0.f) {
        int lo = -K, hi = K + 1;
        while (lo < hi) {
            int mid = lo + ((hi - lo) >> 1);
            if (f_ge0(inv, c0, mid)) hi = mid; else lo = mid + 1;
        }
        *T = lo; *F = 0;
    } else if (inv < 0.f) {
        int lo = -K - 1, hi = K;
        while (lo < hi) {
            int mid = lo + ((hi - lo + 1) >> 1);
            if (f_ge0(inv, c0, mid)) lo = mid; else hi = mid - 1;
        }
        *T = lo + 1; *F = 1;
    } else {
        if (c0 < 0.f) { *T =  K + 1;  *F = 0; }
        else          { *T = -(K+1);  *F = 0; }
    }
}

// ---- pipeline sync helpers ----
__device__ __forceinline__ void block_wait(int* flag, int target)
{
    if (threadIdx.x == 0) {
        while (true) {
            int v;
            asm volatile("ld.acquire.gpu.b32 %0, [%1];" : "=r"(v) : "l"(flag));
            if (v >= target) break;
            __nanosleep(128);
        }
    }
    __syncthreads();
}

__device__ __forceinline__ void block_signal(int* flag, int amt = 1)
{
    __syncthreads();
    if (threadIdx.x == 0) {
        __threadfence();
        atomicAdd(flag, amt);
    }
}

// ---- single fused kernel: precompute + binx + L1 + L2 + L3 + fc ----
// blocks [0,6)       precompute (0: w1, 1: w2, 2..5: w3 quarters)
// blocks [6,1574)    binx     -> d_bx[b]  (49/image)
// blocks [1574,3142) L1       -> d_l1[b]  (49/image), waits d_bx, d_pw1
// blocks [3142,6278) L2       -> d_l2[b]  (98/image), waits d_l1, d_pw2
// blocks [6278,7846) L3 + fc                      , waits d_l2, d_pw3
// All waits point >=1519 blocks backwards; in-order CTA rasterization with a
// ~740-block residency window guarantees forward progress.
#define L1CM 0x070381C0u

__global__ __launch_bounds__(256) void bnn_kernel(
    const float* __restrict__ x,
    const float* w1, const float* w2, const float* w3,
    const float* g1, const float* b1, const float* m1, const float* v1,
    const float* g2, const float* b2, const float* m2, const float* v2,
    const float* g3, const float* b3, const float* m3, const float* v3,
    const float* __restrict__ fcw,
    const float* __restrict__ fcb,
    float* __restrict__ out)
{
    __shared__ __align__(16) char smemraw[12544];
    int t = threadIdx.x;
    int blk = blockIdx.x;

    if (blk < 6) {
        if (blk == 0) {
            // ---- w1 pack + S1 + Finit1 ----
            __shared__ int sF1[32];
            if (t < 32) {
                uint32_t bits = 0;
                for (int ic = 0; ic < 3; ic++)
                    for (int kh = 0; kh < 3; kh++)
                        for (int kw = 0; kw < 3; kw++)
                            if (w1[((t*3 + ic)*3 + kh)*3 + kw] < 0.f)
                                bits |= 1u << ((kh*3 + kw)*3 + ic);
                g_w1[t] = bits;
                int T, F; calc_thresh(g1[t], b1[t], m1[t], v1[t], 27, &T, &F);
                sF1[t] = F;
                for (int bt = 0; bt < 9; bt++) {
                    int vt = bt / 3, hz = bt % 3;
                    int inv = 0;
                    if (vt == 1) inv |= (1|2|4);
                    if (vt == 2) inv |= (64|128|256);
                    if (hz == 1) inv |= (1|8|64);
                    if (hz == 2) inv |= (4|32|256);
                    int nv = 27 - 3*__popc(inv);
                    int corr = 0;
                    for (int tap = 0; tap < 9; tap++)
                        if ((inv >> tap) & 1) corr += __popc((bits >> (tap*3)) & 7u);
                    g_S1[bt*32 + t] = ((nv - T) >> 1) + corr + 1;
                }
            }
            __syncthreads();
            if (t == 0) {
                uint32_t f = 0;
                for (int oc = 0; oc < 32; oc++) f |= ((uint32_t)sF1[oc]) << oc;
                g_Finit1 = f;
            }
            block_signal(&d_pw1);
            return;
        }
        if (blk == 1) {
            // ---- w2 pack + S2 + Finit2 ----
            __shared__ int sF2[64];
            for (int p = t; p < 576; p += 256) {
                int oc = p / 9, tap = p % 9;
                int kh = tap / 3, kw = tap % 3;
                uint32_t bits = 0;
                #pragma unroll 8
                for (int ic = 0; ic < 32; ic++)
                    if (w2[((oc*32 + ic)*3 + kh)*3 + kw] < 0.f) bits |= 1u << ic;
                g_w2[p] = bits;
            }
            __syncthreads();
            if (t < 64) {
                uint32_t wt[9];
                #pragma unroll
                for (int tap = 0; tap < 9; tap++) wt[tap] = g_w2[t*9 + tap];
                int T, F; calc_thresh(g2[t], b2[t], m2[t], v2[t], 288, &T, &F);
                sF2[t] = F;
                for (int bt = 0; bt < 4; bt++) {
                    int inv = 0;
                    if (bt & 1) inv |= (1|2|4);
                    if (bt & 2) inv |= (1|8|64);
                    int nv = 32 * (9 - __popc(inv));
                    int corr = 0;
                    for (int tap = 0; tap < 9; tap++)
                        if ((inv >> tap) & 1) corr += __popc(wt[tap]);
                    g_S2[bt*64 + t] = ((nv - T) >> 1) + corr + 1;
                }
            }
            __syncthreads();
            if (t == 0) {
                uint32_t lo = 0, hi = 0;
                for (int oc = 0; oc < 32; oc++) lo |= ((uint32_t)sF2[oc]) << oc;
                for (int oc = 0; oc < 32; oc++) hi |= ((uint32_t)sF2[oc+32]) << oc;
                g_Finit2lo = lo; g_Finit2hi = hi;
            }
            block_signal(&d_pw2);
            return;
        }
        {
            // ---- blocks 2..5: w3 pack quarter + S3 + F3 ----
            int q = blk - 2;
            for (int pp = t; pp < 288; pp += 256) {
                int p = q*288 + pp;
                int oc = p / 9, tap = p % 9;
                int kh = tap / 3, kw = tap % 3;
                unsigned long long bits = 0;
                #pragma unroll 8
                for (int ic = 0; ic < 64; ic++)
                    if (w3[((oc*64 + ic)*3 + kh)*3 + kw] < 0.f) bits |= 1ull << ic;
                g_w3[p] = bits;
            }
            __syncthreads();
            if (t < 32) {
                int oc = q*32 + t;
                unsigned long long wt[9];
                #pragma unroll
                for (int tap = 0; tap < 9; tap++) wt[tap] = g_w3[oc*9 + tap];
                int T, F; calc_thresh(g3[oc], b3[oc], m3[oc], v3[oc], 576, &T, &F);
                g_F3[oc] = F;
                for (int bt = 0; bt < 4; bt++) {
                    int inv = 0;
                    if (bt & 1) inv |= (1|2|4);
                    if (bt & 2) inv |= (1|8|64);
                    int nv = 64 * (9 - __popc(inv));
                    int corr = 0;
                    for (int tap = 0; tap < 9; tap++)
                        if ((inv >> tap) & 1) corr += __popcll(wt[tap]);
                    g_S3[bt*128 + oc] = ((nv - T) >> 1) + corr + 1;
                }
            }
            block_signal(&d_pw3);
            return;
        }
    }

    if (blk < 1574) {
        // ---------------- binx role: 4 px/thread ----------------
        int i = (blk - 6) * 256 + t;           // NB*P1/4 exact
        int b = i / 12544, rem = i % 12544;
        int oh = rem / 56, ow0 = (rem % 56) * 4;

        const float4* xb = reinterpret_cast<const float4*>(x);
        int base = (b * 3 * P1) >> 2;
        int pidx = (oh * H1 + ow0) >> 2;
        float4 v0 = xb[base + pidx];
        float4 v1 = xb[base + (P1 >> 2) + pidx];
        float4 v2 = xb[base + (P1 >> 1) + pidx];

        uint4 o;
        o.x = (v0.x < 0.f ? 1u:0u) | (v1.x < 0.f ? 2u:0u) | (v2.x < 0.f ? 4u:0u);
        o.y = (v0.y < 0.f ? 1u:0u) | (v1.y < 0.f ? 2u:0u) | (v2.y < 0.f ? 4u:0u);
        o.z = (v0.z < 0.f ? 1u:0u) | (v1.z < 0.f ? 2u:0u) | (v2.z < 0.f ? 4u:0u);
        o.w = (v0.w < 0.f ? 1u:0u) | (v1.w < 0.f ? 2u:0u) | (v2.w < 0.f ? 4u:0u);

        *reinterpret_cast<uint4*>(&g_binx[b*(BXR*BXS) + (oh+1)*BXS + ow0 + 4]) = o;

        block_signal(&d_bx[b]);
        return;
    }

    if (blk < 3142) {
        // ---------------- L1 role: 4 px/thread ----------------
        int lblk = blk - 1574;
        int b = lblk / 49;

        block_wait(&d_bx[b], 49);
        block_wait(&d_pw1, 1);

        uint32_t* sw = reinterpret_cast<uint32_t*>(smemraw);
        int* sS = reinterpret_cast<int*>(smemraw + 128);
        if (t < 32) sw[t] = g_w1[t];
        for (int j = t; j < 9*32; j += 256) sS[j] = g_S1[j];
        __syncthreads();

        int i = lblk * 256 + t;                // NB*224*56 exact
        int rem = i % 12544;
        int oh = rem / 56, g = rem % 56;
        int ow0 = g * 4;

        const uint32_t* bx = g_binx + b*(BXR*BXS) + oh*BXS + ow0 + 3;
        uint32_t c[3][6];
        #pragma unroll
        for (int kh = 0; kh < 3; kh++)
            #pragma unroll
            for (int m = 0; m < 6; m++) c[kh][m] = bx[kh*BXS + m];

        uint32_t xv0 = 0;
        #pragma unroll
        for (int kh = 0; kh < 3; kh++)
            #pragma unroll
            for (int kw = 0; kw < 3; kw++)
                xv0 |= c[kh][kw] << ((kh*3 + kw)*3);

        uint32_t xv1 = ((xv0 >> 3) & ~L1CM) | (c[0][3]<<6) | (c[1][3]<<15) | (c[2][3]<<24);
        uint32_t xv2 = ((xv1 >> 3) & ~L1CM) | (c[0][4]<<6) | (c[1][4]<<15) | (c[2][4]<<24);
        uint32_t xv3 = ((xv2 >> 3) & ~L1CM) | (c[0][5]<<6) | (c[1][5]<<15) | (c[2][5]<<24);

        int vt = (oh == 0) ? 1 : ((oh == 223) ? 2 : 0);
        const int* Sm = &sS[(vt*3) * 32];
        const int* Sa = &sS[(vt*3 + ((g == 0)  ? 1 : 0)) * 32];
        const int* Sb = &sS[(vt*3 + ((g == 55) ? 2 : 0)) * 32];

        uint32_t fi = g_Finit1;
        uint32_t o0 = fi, o1 = fi, o2 = fi, o3 = fi;
        #pragma unroll 8
        for (int oc = 0; oc < 32; oc++) {
            uint32_t w = sw[oc];
            uint32_t mb = 1u << oc;
            int sm = Sm[oc];
            if (__popc(xv0 ^ w) >= Sa[oc]) o0 ^= mb;
            if (__popc(xv1 ^ w) >= sm)     o1 ^= mb;
            if (__popc(xv2 ^ w) >= sm)     o2 ^= mb;
            if (__popc(xv3 ^ w) >= Sb[oc]) o3 ^= mb;
        }
        uint4 ov = make_uint4(o0, o1, o2, o3);
        *reinterpret_cast<uint4*>(
            &g_h1[b*(H1R*H1S) + (oh+1)*H1S + (ow0+4)]) = ov;

        block_signal(&d_l1[b]);
        return;
    }

    if (blk < 6278) {
        // ---------------- L2 role: 1 px/thread, 32 oc per group ----------------
        int lblk = blk - 3142;         // 0..3135
        int b = lblk / 98;
        int sub = lblk % 98;
        int grp = sub / 49;
        int sub2 = sub % 49;

        block_wait(&d_l1[b], 49);
        block_wait(&d_pw2, 1);

        uint4* sw4 = reinterpret_cast<uint4*>(smemraw);
        int* sS = reinterpret_cast<int*>(smemraw + 1536);
        for (int j = t; j < 32*3; j += 256) {
            int oc = j / 3, k = j % 3, base = (grp*32 + oc)*9 + k*4;
            uint4 v;
            v.x = g_w2[base];
            v.y = (k*4 + 1 < 9) ? g_w2[base+1] : 0u;
            v.z = (k*4 + 2 < 9) ? g_w2[base+2] : 0u;
            v.w = (k*4 + 3 < 9) ? g_w2[base+3] : 0u;
            sw4[j] = v;
        }
        for (int j = t; j < 4*32; j += 256) {
            int bt = j >> 5, oc = j & 31;
            sS[j] = g_S2[bt*64 + grp*32 + oc];
        }
        __syncthreads();

        int i = (b*49 + sub2) * 256 + t;
        int rem = i % 12544;
        int oh = rem / 112, ow = rem % 112;

        const uint32_t* h1 = g_h1 + b*(H1R*H1S) + (2*oh)*H1S + 2*ow + 3;
        uint32_t x00 = h1[0],      x01 = h1[1],       x02 = h1[2];
        uint32_t x10 = h1[H1S],    x11 = h1[H1S+1],   x12 = h1[H1S+2];
        uint32_t x20 = h1[2*H1S],  x21 = h1[2*H1S+1], x22 = h1[2*H1S+2];

        int bt = ((oh == 0) ? 1 : 0) + ((ow == 0) ? 2 : 0);
        const int* Sp = &sS[bt * 32];

        uint32_t acc = grp ? g_Finit2hi : g_Finit2lo;

        #pragma unroll 8
        for (int oc = 0; oc < 32; oc++) {
            uint4 a = sw4[oc*3], bq = sw4[oc*3+1], cq = sw4[oc*3+2];
            uint32_t t0 = x00^a.x,  t1 = x01^a.y,  t2 = x02^a.z;
            uint32_t t3 = x10^a.w,  t4 = x11^bq.x, t5 = x12^bq.y;
            uint32_t t6 = x20^bq.z, t7 = x21^bq.w, t8 = x22^cq.x;
            uint32_t s0 = t0^t1^t2, k0 = MAJ(t0,t1,t2);
            uint32_t s1 = t3^t4^t5, k1 = MAJ(t3,t4,t5);
            uint32_t s2 = t6^t7^t8, k2 = MAJ(t6,t7,t8);
            uint32_t s3 = s0^s1^s2, k3 = MAJ(s0,s1,s2);
            uint32_t s4 = k0^k1^k2, k4 = MAJ(k0,k1,k2);
            int tot = __popc(s3) + ((__popc(k3) + __popc(s4)) << 1)
                    + (__popc(k4) << 2);
            if (tot >= Sp[oc]) acc ^= 1u << oc;
        }
        uint32_t* dst = reinterpret_cast<uint32_t*>(
            &g_h2[b*(H2R*H2S) + (oh+1)*H2S + (ow+1)]);
        dst[grp] = acc;

        block_signal(&d_l2[b]);
        return;
    }

    {
        // ------- L3 role: warp = 32 px, 32 oc (quarter); CSA popcount + fc ----
        int lblk = blk - 6278;         // 0..1567
        int b = lblk / 49;

        block_wait(&d_l2[b], 98);
        block_wait(&d_pw3, 4);

        ulonglong2* sw2 = reinterpret_cast<ulonglong2*>(smemraw);
        int* sS = reinterpret_cast<int*>(smemraw + 10240);
        for (int j = t; j < 128*5; j += 256) {
            int oc = j / 5, s2 = j % 5, base = oc*9 + s2*2;
            ulonglong2 v;
            v.x = g_w3[base];
            v.y = (s2*2 + 1 < 9) ? g_w3[base+1] : 0ull;
            sw2[j] = v;
        }
        for (int j = t; j < 4*128; j += 256) sS[j] = g_S3[j];
        __syncthreads();

        int i = lblk * 256 + t;
        int wid = i >> 5, lane = i & 31;
        int quarter = wid & 3;
        int pw = wid >> 2;
        int q = (pw % 98) * 32 + lane;
        int oh = q / H3, ow = q % H3;

        const unsigned long long* h2 = g_h2 + b*(H2R*H2S) + (2*oh)*H2S + 2*ow;
        unsigned long long c00 = h2[0],       c01 = h2[1],       c02 = h2[2];
        unsigned long long c10 = h2[H2S],     c11 = h2[H2S+1],   c12 = h2[H2S+2];
        unsigned long long c20 = h2[2*H2S],   c21 = h2[2*H2S+1], c22 = h2[2*H2S+2];

        int bt = ((oh == 0) ? 1 : 0) + ((ow == 0) ? 2 : 0);
        const int* Sp = &sS[bt*128 + quarter*32];
        const ulonglong2* wbase = &sw2[quarter*32*5];

        int r = 0;
        #pragma unroll 4
        for (int k = 0; k < 32; k++) {
            const ulonglong2* wp = wbase + k*5;
            ulonglong2 q0 = wp[0], q1 = wp[1], q2 = wp[2], q3 = wp[3], q4 = wp[4];
            unsigned long long t0 = c00^q0.x, t1 = c01^q0.y, t2 = c02^q1.x;
            unsigned long long t3 = c10^q1.y, t4 = c11^q2.x, t5 = c12^q2.y;
            unsigned long long t6 = c20^q3.x, t7 = c21^q3.y, t8 = c22^q4.x;
            unsigned long long s0w = t0^t1^t2, k0w = MAJ(t0,t1,t2);
            unsigned long long s1w = t3^t4^t5, k1w = MAJ(t3,t4,t5);
            unsigned long long s2w = t6^t7^t8, k2w = MAJ(t6,t7,t8);
            unsigned long long s3w = s0w^s1w^s2w, k3w = MAJ(s0w,s1w,s2w);
            unsigned long long s4w = k0w^k1w^k2w, k4w = MAJ(k0w,k1w,k2w);
            int tot = __popcll(s3w) + ((__popcll(k3w) + __popcll(s4w)) << 1)
                    + (__popcll(k4w) << 2);
            unsigned bal = __ballot_sync(0xFFFFFFFFu, tot >= Sp[k]);
            if (k == lane) r = __popc(bal);
        }

        int oc = quarter*32 + lane;
        if (g_F3[oc]) r = 32 - r;
        atomicAdd(&g_cnt[b*128 + oc], r);

        // ---- fused fc + self-clean: last completing block of this image ----
        __shared__ int slast;
        __syncthreads();
        if (t == 0) {
            __threadfence();
            int old = atomicAdd(&g_done[b], 1);
            slast = (old == 48);
        }
        __syncthreads();
        if (slast) {
            if (t < 32) {
                int lane2 = t;
                float u0 = 0.f, u1 = 0.f;
                #pragma unroll
                for (int j = 0; j < 4; j++) {
                    int c = lane2 * 4 + j;
                    float mean = (float)(P3 - 2*g_cnt[b*128 + c]) / (float)P3;
                    u0 += mean * fcw[c];
                    u1 += mean * fcw[128 + c];
                }
                #pragma unroll
                for (int off = 16; off > 0; off >>= 1) {
                    u0 += __shfl_down_sync(0xFFFFFFFFu, u0, off);
                    u1 += __shfl_down_sync(0xFFFFFFFFu, u1, off);
                }
                if (lane2 == 0) {
                    out[b*2]     = fcb[0] + u0;
                    out[b*2 + 1] = fcb[1] + u1;
                }
            }
            __syncthreads();
            // self-clean per-image state for deterministic graph replay
            if (t < 128) g_cnt[b*128 + t] = 0;
            if (t == 0) {
                g_done[b] = 0; d_bx[b] = 0; d_l1[b] = 0; d_l2[b] = 0;
                __threadfence();
                int fin = atomicAdd(&g_fcdone, 1);
                if (fin == NB - 1) {           // last image: reset globals
                    d_pw1 = 0; d_pw2 = 0; d_pw3 = 0; g_fcdone = 0;
                    __threadfence();
                }
            }
        }
    }
}

// ---------------- launch ----------------
extern "C" void kernel_launch(void* const* d_in, const int* in_sizes, int n_in,
                              void* d_out, int out_size)
{
    const float* x   = (const float*)d_in[0];
    const float* w1  = (const float*)d_in[1];
    const float* w2  = (const float*)d_in[2];
    const float* w3  = (const float*)d_in[3];
    const float* g1  = (const float*)d_in[4];
    const float* b1  = (const float*)d_in[5];
    const float* m1  = (const float*)d_in[6];
    const float* v1  = (const float*)d_in[7];
    const float* g2  = (const float*)d_in[8];
    const float* b2  = (const float*)d_in[9];
    const float* m2  = (const float*)d_in[10];
    const float* v2  = (const float*)d_in[11];
    const float* g3  = (const float*)d_in[12];
    const float* b3  = (const float*)d_in[13];
    const float* m3  = (const float*)d_in[14];
    const float* v3  = (const float*)d_in[15];
    const float* fcw = (const float*)d_in[16];
    const float* fcb = (const float*)d_in[17];
    float* out = (float*)d_out;

    bnn_kernel<<<7846, 256>>>(x, w1, w2, w3,
                              g1, b1, m1, v1,
                              g2, b2, m2, v2,
                              g3, b3, m3, v3,
                              fcw, fcb, out);
}